// round 2
// baseline (speedup 1.0000x reference)
#include <cuda_runtime.h>

// ---------------- problem constants ----------------
#define NN   84              // nodes
#define PP   3486            // pairs = NN*(NN-1)/2
#define HSZ  2048
#define H2   1024
#define G3H  6144            // 3*HSZ

// ---------------- device scratch (static, no allocation) ----------------
__device__ float g_gi[NN * G3H];        //  2.1 MB  per-node input gates
__device__ float g_gh[PP * G3H];        // 85.7 MB  hidden-gate GEMM output (reused later)
__device__ float g_h [PP * HSZ];        // 28.6 MB  hidden state
__device__ float g_y [PP * HSZ];        // 28.6 MB  layer-1 activations
__device__ double g_acc[6];             // LN sum/sumsq accumulators (3 layers)
__device__ int   g_iu[PP];
__device__ int   g_ju[PP];

// ---------------- packed f32x2 helpers ----------------
__device__ __forceinline__ unsigned long long pk2(float lo, float hi) {
    unsigned long long r;
    asm("mov.b64 %0, {%1, %2};" : "=l"(r) : "f"(lo), "f"(hi));
    return r;
}
__device__ __forceinline__ void fma2(unsigned long long& d,
                                     unsigned long long a, unsigned long long b) {
    asm("fma.rn.f32x2 %0, %1, %2, %0;" : "+l"(d) : "l"(a), "l"(b));
}
__device__ __forceinline__ float2 unpk2(unsigned long long v) {
    float lo, hi;
    asm("mov.b64 {%0, %1}, %2;" : "=f"(lo), "=f"(hi) : "l"(v));
    return make_float2(lo, hi);
}

__device__ __forceinline__ float sigm(float x) { return 1.0f / (1.0f + expf(-x)); }

// ---------------- init: zero LN accumulators + build pair index tables ----------------
__global__ void k_init() {
    int t = blockIdx.x * blockDim.x + threadIdx.x;
    if (t < 6) g_acc[t] = 0.0;
    if (t < NN * NN) {
        int i = t / NN, j = t % NN;
        if (j > i) {
            int p = i * (NN - 1) - i * (i - 1) / 2 + (j - i - 1);
            g_iu[p] = i;
            g_ju[p] = j;
        }
    }
}

// ---------------- tiled SGEMM: C[M,N] = A[M,K] @ B[N,K]^T + bias ----------------
// 128x128 block tile, BK=16, 256 threads, 8x8 per-thread micro-tile via fma.rn.f32x2.
// Requires N % 128 == 0 and K % 16 == 0 (true for all call sites). M is guarded.
// SLOT >= 0: accumulate sum/sumsq of the (post-ReLU) outputs into g_acc[2*SLOT(+1)].
template <bool RELU, int SLOT>
__global__ __launch_bounds__(256)
void k_gemm(const float* __restrict__ A, const float* __restrict__ B,
            const float* __restrict__ bias, float* __restrict__ C,
            int M, int N, int K)
{
    __shared__ float As[16][132];
    __shared__ float Bs[16][132];

    const int tid = threadIdx.x;
    const int tx  = tid & 15;        // 0..15  -> column group
    const int ty  = tid >> 4;        // 0..15  -> row group
    const int m0  = blockIdx.y * 128;
    const int n0  = blockIdx.x * 128;

    unsigned long long acc[8][4];
#pragma unroll
    for (int i = 0; i < 8; i++)
#pragma unroll
        for (int j = 0; j < 4; j++) acc[i][j] = 0ULL;

    for (int kt = 0; kt < K; kt += 16) {
        __syncthreads();
#pragma unroll
        for (int q = 0; q < 2; q++) {
            int fi  = tid + q * 256;     // 0..511 float4 slots
            int row = fi >> 2;           // 0..127
            int kq  = fi & 3;            // 0..3  (float4 within the 16-wide K tile)
            float4 av = make_float4(0.f, 0.f, 0.f, 0.f);
            int gr = m0 + row;
            if (gr < M)
                av = *(const float4*)(A + (size_t)gr * K + kt + kq * 4);
            As[kq * 4 + 0][row] = av.x;
            As[kq * 4 + 1][row] = av.y;
            As[kq * 4 + 2][row] = av.z;
            As[kq * 4 + 3][row] = av.w;
            float4 bv = *(const float4*)(B + (size_t)(n0 + row) * K + kt + kq * 4);
            Bs[kq * 4 + 0][row] = bv.x;
            Bs[kq * 4 + 1][row] = bv.y;
            Bs[kq * 4 + 2][row] = bv.z;
            Bs[kq * 4 + 3][row] = bv.w;
        }
        __syncthreads();

#pragma unroll
        for (int kk = 0; kk < 16; kk++) {
            float4 a0 = *(const float4*)&As[kk][ty * 8];
            float4 a1 = *(const float4*)&As[kk][ty * 8 + 4];
            float4 b0 = *(const float4*)&Bs[kk][tx * 8];
            float4 b1 = *(const float4*)&Bs[kk][tx * 8 + 4];
            unsigned long long bp0 = pk2(b0.x, b0.y);
            unsigned long long bp1 = pk2(b0.z, b0.w);
            unsigned long long bp2 = pk2(b1.x, b1.y);
            unsigned long long bp3 = pk2(b1.z, b1.w);
            float av[8] = {a0.x, a0.y, a0.z, a0.w, a1.x, a1.y, a1.z, a1.w};
#pragma unroll
            for (int i = 0; i < 8; i++) {
                unsigned long long ap = pk2(av[i], av[i]);
                fma2(acc[i][0], ap, bp0);
                fma2(acc[i][1], ap, bp1);
                fma2(acc[i][2], ap, bp2);
                fma2(acc[i][3], ap, bp3);
            }
        }
    }

    // epilogue: bias, relu, store, (optional) LN-stat reduction
    double lsum = 0.0, lsq = 0.0;
#pragma unroll
    for (int i = 0; i < 8; i++) {
        int r = m0 + ty * 8 + i;
        if (r < M) {
            float* crow = C + (size_t)r * N + n0 + tx * 8;
            const float* brow = bias + n0 + tx * 8;
#pragma unroll
            for (int j2 = 0; j2 < 4; j2++) {
                float2 v = unpk2(acc[i][j2]);
                float c0 = v.x + brow[j2 * 2];
                float c1 = v.y + brow[j2 * 2 + 1];
                if (RELU) { c0 = fmaxf(c0, 0.f); c1 = fmaxf(c1, 0.f); }
                crow[j2 * 2]     = c0;
                crow[j2 * 2 + 1] = c1;
                if (SLOT >= 0) {
                    lsum += (double)c0 + (double)c1;
                    lsq  += (double)c0 * c0 + (double)c1 * c1;
                }
            }
        }
    }
    if (SLOT >= 0) {
#pragma unroll
        for (int off = 16; off; off >>= 1) {
            lsum += __shfl_down_sync(0xffffffffu, lsum, off);
            lsq  += __shfl_down_sync(0xffffffffu, lsq,  off);
        }
        if ((tid & 31) == 0) {
            atomicAdd(&g_acc[SLOT * 2],     lsum);
            atomicAdd(&g_acc[SLOT * 2 + 1], lsq);
        }
    }
}

// ---------------- GRU elementwise combine ----------------
// STEP 0: gather gi via iu (first GRU step), STEP 1: via ju (second step).
template <int STEP>
__global__ void k_gru(const float* __restrict__ hin, float* __restrict__ hout)
{
    int idx = blockIdx.x * blockDim.x + threadIdx.x;
    if (idx >= PP * HSZ) return;
    int p = idx / HSZ;
    int j = idx - p * HSZ;
    int node = (STEP == 0) ? g_iu[p] : g_ju[p];
    const float* gi = g_gi + (size_t)node * G3H;
    const float* gh = g_gh + (size_t)p * G3H;
    float r = sigm(gi[j]           + gh[j]);
    float z = sigm(gi[j + HSZ]     + gh[j + HSZ]);
    float n = tanhf(gi[j + 2*HSZ]  + r * gh[j + 2*HSZ]);
    hout[idx] = (1.0f - z) * n + z * hin[idx];
}

// ---------------- full-tensor LayerNorm apply (stats already in g_acc) ----------------
__global__ void k_norm(float* __restrict__ buf, const float* __restrict__ w,
                       const float* __restrict__ b, int count, int slot)
{
    double sum = g_acc[slot * 2];
    double sq  = g_acc[slot * 2 + 1];
    double mu  = sum / (double)count;
    double var = sq / (double)count - mu * mu;
    float rs  = rsqrtf((float)var + 1e-5f);
    float fmu = (float)mu;
    for (int i = blockIdx.x * blockDim.x + threadIdx.x; i < count;
         i += gridDim.x * blockDim.x) {
        buf[i] = (buf[i] - fmu) * rs * w[i] + b[i];
    }
}

// ---------------- final: vals = sigmoid(h3 @ W4^T + b4), symmetric scatter ----------------
__global__ void k_out(const float* __restrict__ h3, const float* __restrict__ w4,
                      const float* __restrict__ b4, float* __restrict__ out)
{
    int w    = (blockIdx.x * blockDim.x + threadIdx.x) >> 5;
    int lane = threadIdx.x & 31;
    if (w >= NN * NN) return;
    int i = w / NN, j = w % NN;
    if (i == j) { if (lane == 0) out[w] = 0.f; return; }
    int i0 = min(i, j), j0 = max(i, j);
    int p = i0 * (NN - 1) - i0 * (i0 - 1) / 2 + (j0 - i0 - 1);
    const float* hr = h3 + (size_t)p * H2;
    float s = 0.f;
    for (int t = lane; t < H2; t += 32) s += hr[t] * w4[t];
#pragma unroll
    for (int off = 16; off; off >>= 1) s += __shfl_down_sync(0xffffffffu, s, off);
    if (lane == 0) out[w] = 1.0f / (1.0f + expf(-(s + b4[0])));
}

// ---------------- host launch ----------------
extern "C" void kernel_launch(void* const* d_in, const int* in_sizes, int n_in,
                              void* d_out, int out_size)
{
    const float* x    = (const float*)d_in[0];
    const float* hid  = (const float*)d_in[1];
    const float* Wih  = (const float*)d_in[2];
    const float* Whh  = (const float*)d_in[3];
    const float* bih  = (const float*)d_in[4];
    const float* bhh  = (const float*)d_in[5];
    const float* W1   = (const float*)d_in[6];
    const float* b1   = (const float*)d_in[7];
    const float* ln1w = (const float*)d_in[8];
    const float* ln1b = (const float*)d_in[9];
    const float* W2   = (const float*)d_in[10];
    const float* b2   = (const float*)d_in[11];
    const float* ln2w = (const float*)d_in[12];
    const float* ln2b = (const float*)d_in[13];
    const float* W3   = (const float*)d_in[14];
    const float* b3   = (const float*)d_in[15];
    const float* ln3w = (const float*)d_in[16];
    const float* ln3b = (const float*)d_in[17];
    const float* W4   = (const float*)d_in[18];
    const float* b4   = (const float*)d_in[19];
    float* out = (float*)d_out;

    float *p_gi, *p_gh, *p_h, *p_y;
    cudaGetSymbolAddress((void**)&p_gi, g_gi);
    cudaGetSymbolAddress((void**)&p_gh, g_gh);
    cudaGetSymbolAddress((void**)&p_h,  g_h);
    cudaGetSymbolAddress((void**)&p_y,  g_y);
    float* p_t  = p_gh;                    // [PP, H2]  (g_gh is free after GRU2)
    float* p_t2 = p_gh + (size_t)PP * H2;  // [PP, H2]

    // 0) init pair tables + zero LN accumulators
    k_init<<<(NN * NN + 255) / 256, 256>>>();

    // 1) gi_node = x @ Wih^T + bih            [84, 6144]
    k_gemm<false, -1><<<dim3(G3H / 128, 1), 256>>>(x, Wih, bih, p_gi, NN, G3H, 64);

    const int MB = (PP + 127) / 128;  // 28

    // 2) GRU step 1: gh = hid @ Whh^T + bhh, combine -> g_h
    k_gemm<false, -1><<<dim3(G3H / 128, MB), 256>>>(hid, Whh, bhh, p_gh, PP, G3H, HSZ);
    k_gru<0><<<(PP * HSZ + 255) / 256, 256>>>(hid, p_h);

    // 3) GRU step 2: gh = g_h @ Whh^T + bhh, combine in place -> g_h
    k_gemm<false, -1><<<dim3(G3H / 128, MB), 256>>>(p_h, Whh, bhh, p_gh, PP, G3H, HSZ);
    k_gru<1><<<(PP * HSZ + 255) / 256, 256>>>(p_h, p_h);

    // 4) layer 1: relu(h @ W1^T + b1) -> g_y, full LN (stats fused in epilogue)
    k_gemm<true, 0><<<dim3(HSZ / 128, MB), 256>>>(p_h, W1, b1, p_y, PP, HSZ, HSZ);
    k_norm<<<2048, 256>>>(p_y, ln1w, ln1b, PP * HSZ, 0);

    // 5) layer 2: relu(y @ W2^T + b2) -> t, full LN
    k_gemm<true, 1><<<dim3(H2 / 128, MB), 256>>>(p_y, W2, b2, p_t, PP, H2, HSZ);
    k_norm<<<2048, 256>>>(p_t, ln2w, ln2b, PP * H2, 1);

    // 6) layer 3: relu(t @ W3^T + b3) -> t2, full LN
    k_gemm<true, 2><<<dim3(H2 / 128, MB), 256>>>(p_t, W3, b3, p_t2, PP, H2, H2);
    k_norm<<<2048, 256>>>(p_t2, ln3w, ln3b, PP * H2, 2);

    // 7) final sigmoid dot + symmetric scatter into [84, 84]
    k_out<<<(NN * NN * 32 + 255) / 256, 256>>>(p_t2, W4, b4, out);
}

// round 4
// speedup vs baseline: 2.0709x; 2.0709x over previous
#include <cuda_runtime.h>
#include <cuda_bf16.h>
#include <stdint.h>

// ---------------- problem constants ----------------
#define NN   84
#define PP   3486
#define HSZ  2048
#define H2   1024
#define G3H  6144

// ---------------- device scratch ----------------
__device__ float g_gi[NN * G3H];
__device__ float g_gh[PP * G3H];      // GEMM outputs; reused as t / t2 later
__device__ float g_h [PP * HSZ];
__device__ float g_y [PP * HSZ];
__device__ double g_acc[6];
__device__ int   g_iu[PP];
__device__ int   g_ju[PP];
__device__ __nv_bfloat16 g_ahi[PP * HSZ];   // activation bf16 hi
__device__ __nv_bfloat16 g_alo[PP * HSZ];   // activation bf16 lo
__device__ __nv_bfloat16 g_bhi[G3H * HSZ];  // weight bf16 hi
__device__ __nv_bfloat16 g_blo[G3H * HSZ];  // weight bf16 lo

__device__ __forceinline__ float sigm(float x) { return 1.0f / (1.0f + expf(-x)); }

__device__ __forceinline__ void split_bf(float x, __nv_bfloat16& h, __nv_bfloat16& l) {
    h = __float2bfloat16(x);
    l = __float2bfloat16(x - __bfloat162float(h));
}

__device__ __forceinline__ uint32_t s2u(const void* p) {
    uint32_t a;
    asm("{ .reg .u64 t; cvta.to.shared.u64 t, %1; cvt.u32.u64 %0, t; }" : "=r"(a) : "l"(p));
    return a;
}

// ---------------- packed f32x2 helpers (for small f32 GEMM) ----------------
__device__ __forceinline__ unsigned long long pk2(float lo, float hi) {
    unsigned long long r;
    asm("mov.b64 %0, {%1, %2};" : "=l"(r) : "f"(lo), "f"(hi));
    return r;
}
__device__ __forceinline__ void fma2(unsigned long long& d,
                                     unsigned long long a, unsigned long long b) {
    asm("fma.rn.f32x2 %0, %1, %2, %0;" : "+l"(d) : "l"(a), "l"(b));
}
__device__ __forceinline__ float2 unpk2(unsigned long long v) {
    float lo, hi;
    asm("mov.b64 {%0, %1}, %2;" : "=f"(lo), "=f"(hi) : "l"(v));
    return make_float2(lo, hi);
}

// ---------------- init ----------------
__global__ void k_init() {
    int t = blockIdx.x * blockDim.x + threadIdx.x;
    if (t < 6) g_acc[t] = 0.0;
    if (t < NN * NN) {
        int i = t / NN, j = t % NN;
        if (j > i) {
            int p = i * (NN - 1) - i * (i - 1) / 2 + (j - i - 1);
            g_iu[p] = i;
            g_ju[p] = j;
        }
    }
}

// ---------------- f32 -> bf16 hi/lo convert ----------------
__global__ void k_conv(const float* __restrict__ in, __nv_bfloat16* __restrict__ hi,
                       __nv_bfloat16* __restrict__ lo, int n) {
    int i = blockIdx.x * blockDim.x + threadIdx.x;
    if (i < n) {
        __nv_bfloat16 h, l;
        split_bf(in[i], h, l);
        hi[i] = h;
        lo[i] = l;
    }
}

// ================= bf16x3 mma.sync GEMM =================
// C[M,N] = A[M,K] @ B[N,K]^T + bias (A,B given as bf16 hi/lo pairs).
// CTA 128x128, BK=32, 256 threads, warp grid 4(M) x 2(N), warp tile 32x64.
// SMEM: 4 matrices (Ahi,Alo,Bhi,Blo) x 128 rows x 80B (32 bf16 + pad), 2 stages.
#define LDB        80
#define MAT_BYTES  (128 * LDB)      // 10240
#define STAGE_BYTES (4 * MAT_BYTES) // 40960
#define GSMEM      (2 * STAGE_BYTES)

#define LDSM4(R, A) \
    asm volatile("ldmatrix.sync.aligned.m8n8.x4.shared.b16 {%0,%1,%2,%3}, [%4];" \
        : "=r"((R)[0]), "=r"((R)[1]), "=r"((R)[2]), "=r"((R)[3]) : "r"(A))
#define LDSM4P(R0, R1, A) \
    asm volatile("ldmatrix.sync.aligned.m8n8.x4.shared.b16 {%0,%1,%2,%3}, [%4];" \
        : "=r"((R0)[0]), "=r"((R0)[1]), "=r"((R1)[0]), "=r"((R1)[1]) : "r"(A))
#define MMA(D, Aa, Bb) \
    asm volatile("mma.sync.aligned.m16n8k16.row.col.f32.bf16.bf16.f32 " \
        "{%0,%1,%2,%3},{%4,%5,%6,%7},{%8,%9},{%0,%1,%2,%3};" \
        : "+f"((D)[0]), "+f"((D)[1]), "+f"((D)[2]), "+f"((D)[3]) \
        : "r"((Aa)[0]), "r"((Aa)[1]), "r"((Aa)[2]), "r"((Aa)[3]), \
          "r"((Bb)[0]), "r"((Bb)[1]))

__device__ __forceinline__ void g_issue(
    uint32_t sbase, int s,
    const __nv_bfloat16* Ahi, const __nv_bfloat16* Alo,
    const __nv_bfloat16* Bhi, const __nv_bfloat16* Blo,
    int m0, int n0, int M, int K, int kt, int tid)
{
    const __nv_bfloat16* bases[4] = {Ahi, Alo, Bhi, Blo};
#pragma unroll
    for (int i = 0; i < 8; i++) {
        int cid = tid + i * 256;
        int mat = cid >> 9;
        int r   = (cid >> 2) & 127;
        int ch  = cid & 3;
        int row, sz;
        if (mat < 2) {
            row = m0 + r;
            sz  = (row < M) ? 16 : 0;
            if (row >= M) row = M - 1;
        } else {
            row = n0 + r;
            sz  = 16;
        }
        const __nv_bfloat16* gp = bases[mat] + (size_t)row * K + kt * 32 + ch * 8;
        uint32_t sa = sbase + s * STAGE_BYTES + mat * MAT_BYTES + r * LDB + ch * 16;
        asm volatile("cp.async.cg.shared.global [%0], [%1], 16, %2;"
                     :: "r"(sa), "l"(gp), "r"(sz));
    }
}

template <bool RELU, int SLOT>
__global__ __launch_bounds__(256)
void k_bgemm(const __nv_bfloat16* __restrict__ Ahi, const __nv_bfloat16* __restrict__ Alo,
             const __nv_bfloat16* __restrict__ Bhi, const __nv_bfloat16* __restrict__ Blo,
             const float* __restrict__ bias, float* __restrict__ C,
             int M, int N, int K)
{
    extern __shared__ char smem[];
    const uint32_t sbase = s2u(smem);
    const int tid  = threadIdx.x;
    const int wid  = tid >> 5;
    const int lane = tid & 31;
    const int m0 = blockIdx.y * 128;
    const int n0 = blockIdx.x * 128;
    const int wm = wid & 3;       // 0..3 -> 32 M rows
    const int wn = wid >> 2;      // 0..1 -> 64 N cols

    float acc[2][8][4];
#pragma unroll
    for (int a = 0; a < 2; a++)
#pragma unroll
        for (int b = 0; b < 8; b++)
#pragma unroll
            for (int c = 0; c < 4; c++) acc[a][b][c] = 0.f;

    const int NKT = K >> 5;
    g_issue(sbase, 0, Ahi, Alo, Bhi, Blo, m0, n0, M, K, 0, tid);
    asm volatile("cp.async.commit_group;" ::: "memory");
    g_issue(sbase, 1, Ahi, Alo, Bhi, Blo, m0, n0, M, K, 1, tid);
    asm volatile("cp.async.commit_group;" ::: "memory");

    // ldmatrix lane addresses
    const uint32_t a_lane = (uint32_t)((wm * 32 + (lane & 15)) * LDB + (lane >> 4) * 16);
    const uint32_t b_lane = (uint32_t)((wn * 64 + (lane >> 4) * 8 + (lane & 7)) * LDB
                                       + ((lane >> 3) & 1) * 16);

    for (int kt = 0; kt < NKT; kt++) {
        const int s = kt & 1;
        if (kt < NKT - 1) asm volatile("cp.async.wait_group 1;" ::: "memory");
        else              asm volatile("cp.async.wait_group 0;" ::: "memory");
        __syncthreads();
        const uint32_t sb = sbase + s * STAGE_BYTES;

#pragma unroll
        for (int k16 = 0; k16 < 2; k16++) {
            uint32_t ah[2][4], al[2][4];
#pragma unroll
            for (int mt = 0; mt < 2; mt++) {
                uint32_t aadr = sb + a_lane + mt * (16 * LDB) + k16 * 32;
                LDSM4(ah[mt], aadr);
                LDSM4(al[mt], aadr + MAT_BYTES);
            }
            uint32_t bh[8][2], bl[8][2];
#pragma unroll
            for (int ntb = 0; ntb < 8; ntb += 2) {
                uint32_t badr = sb + 2 * MAT_BYTES + b_lane + ntb * (8 * LDB) + k16 * 32;
                LDSM4P(bh[ntb], bh[ntb + 1], badr);
                LDSM4P(bl[ntb], bl[ntb + 1], badr + MAT_BYTES);
            }
#pragma unroll
            for (int mt = 0; mt < 2; mt++)
#pragma unroll
                for (int nt = 0; nt < 8; nt++) {
                    MMA(acc[mt][nt], ah[mt], bh[nt]);   // hi * hi
                    MMA(acc[mt][nt], ah[mt], bl[nt]);   // hi * lo
                    MMA(acc[mt][nt], al[mt], bh[nt]);   // lo * hi
                }
        }
        if (kt + 2 < NKT) {
            __syncthreads();
            g_issue(sbase, s, Ahi, Alo, Bhi, Blo, m0, n0, M, K, kt + 2, tid);
            asm volatile("cp.async.commit_group;" ::: "memory");
        }
    }

    // ---------------- epilogue ----------------
    double lsum = 0.0, lsq = 0.0;
    const int rb = m0 + wm * 32 + (lane >> 2);
    const int cb = n0 + wn * 64 + (lane & 3) * 2;
#pragma unroll
    for (int mt = 0; mt < 2; mt++) {
#pragma unroll
        for (int half = 0; half < 2; half++) {
            int r = rb + mt * 16 + half * 8;
            if (r < M) {
                float* crow = C + (size_t)r * N;
#pragma unroll
                for (int nt = 0; nt < 8; nt++) {
                    int c = cb + nt * 8;
                    float v0 = acc[mt][nt][half * 2]     + bias[c];
                    float v1 = acc[mt][nt][half * 2 + 1] + bias[c + 1];
                    if (RELU) { v0 = fmaxf(v0, 0.f); v1 = fmaxf(v1, 0.f); }
                    crow[c]     = v0;
                    crow[c + 1] = v1;
                    if (SLOT >= 0) {
                        lsum += (double)v0 + (double)v1;
                        lsq  += (double)v0 * v0 + (double)v1 * v1;
                    }
                }
            }
        }
    }
    if (SLOT >= 0) {
#pragma unroll
        for (int off = 16; off; off >>= 1) {
            lsum += __shfl_down_sync(0xffffffffu, lsum, off);
            lsq  += __shfl_down_sync(0xffffffffu, lsq,  off);
        }
        if (lane == 0) {
            atomicAdd(&g_acc[SLOT * 2],     lsum);
            atomicAdd(&g_acc[SLOT * 2 + 1], lsq);
        }
    }
}

// ---------------- f32 SGEMM (small; GEMM1 only) ----------------
template <bool RELU, int SLOT>
__global__ __launch_bounds__(256)
void k_gemm(const float* __restrict__ A, const float* __restrict__ B,
            const float* __restrict__ bias, float* __restrict__ C,
            int M, int N, int K)
{
    __shared__ float As[16][132];
    __shared__ float Bs[16][132];
    const int tid = threadIdx.x;
    const int tx  = tid & 15;
    const int ty  = tid >> 4;
    const int m0  = blockIdx.y * 128;
    const int n0  = blockIdx.x * 128;

    unsigned long long acc[8][4];
#pragma unroll
    for (int i = 0; i < 8; i++)
#pragma unroll
        for (int j = 0; j < 4; j++) acc[i][j] = 0ULL;

    for (int kt = 0; kt < K; kt += 16) {
        __syncthreads();
#pragma unroll
        for (int q = 0; q < 2; q++) {
            int fi  = tid + q * 256;
            int row = fi >> 2;
            int kq  = fi & 3;
            float4 av = make_float4(0.f, 0.f, 0.f, 0.f);
            int gr = m0 + row;
            if (gr < M)
                av = *(const float4*)(A + (size_t)gr * K + kt + kq * 4);
            As[kq * 4 + 0][row] = av.x;
            As[kq * 4 + 1][row] = av.y;
            As[kq * 4 + 2][row] = av.z;
            As[kq * 4 + 3][row] = av.w;
            float4 bv = *(const float4*)(B + (size_t)(n0 + row) * K + kt + kq * 4);
            Bs[kq * 4 + 0][row] = bv.x;
            Bs[kq * 4 + 1][row] = bv.y;
            Bs[kq * 4 + 2][row] = bv.z;
            Bs[kq * 4 + 3][row] = bv.w;
        }
        __syncthreads();
#pragma unroll
        for (int kk = 0; kk < 16; kk++) {
            float4 a0 = *(const float4*)&As[kk][ty * 8];
            float4 a1 = *(const float4*)&As[kk][ty * 8 + 4];
            float4 b0 = *(const float4*)&Bs[kk][tx * 8];
            float4 b1 = *(const float4*)&Bs[kk][tx * 8 + 4];
            unsigned long long bp0 = pk2(b0.x, b0.y);
            unsigned long long bp1 = pk2(b0.z, b0.w);
            unsigned long long bp2 = pk2(b1.x, b1.y);
            unsigned long long bp3 = pk2(b1.z, b1.w);
            float av[8] = {a0.x, a0.y, a0.z, a0.w, a1.x, a1.y, a1.z, a1.w};
#pragma unroll
            for (int i = 0; i < 8; i++) {
                unsigned long long ap = pk2(av[i], av[i]);
                fma2(acc[i][0], ap, bp0);
                fma2(acc[i][1], ap, bp1);
                fma2(acc[i][2], ap, bp2);
                fma2(acc[i][3], ap, bp3);
            }
        }
    }
#pragma unroll
    for (int i = 0; i < 8; i++) {
        int r = m0 + ty * 8 + i;
        if (r < M) {
            float* crow = C + (size_t)r * N + n0 + tx * 8;
            const float* brow = bias + n0 + tx * 8;
#pragma unroll
            for (int j2 = 0; j2 < 4; j2++) {
                float2 v = unpk2(acc[i][j2]);
                float c0 = v.x + brow[j2 * 2];
                float c1 = v.y + brow[j2 * 2 + 1];
                if (RELU) { c0 = fmaxf(c0, 0.f); c1 = fmaxf(c1, 0.f); }
                crow[j2 * 2]     = c0;
                crow[j2 * 2 + 1] = c1;
            }
        }
    }
}

// ---------------- GRU elementwise combine (+ fused bf16 split) ----------------
template <int STEP, bool WF32>
__global__ void k_gru(const float* __restrict__ hin, float* __restrict__ hout,
                      __nv_bfloat16* __restrict__ ohi, __nv_bfloat16* __restrict__ olo)
{
    int idx = blockIdx.x * blockDim.x + threadIdx.x;
    if (idx >= PP * HSZ) return;
    int p = idx / HSZ;
    int j = idx - p * HSZ;
    int node = (STEP == 0) ? g_iu[p] : g_ju[p];
    const float* gi = g_gi + (size_t)node * G3H;
    const float* gh = g_gh + (size_t)p * G3H;
    float r = sigm(gi[j]            + gh[j]);
    float z = sigm(gi[j + HSZ]      + gh[j + HSZ]);
    float n = tanhf(gi[j + 2 * HSZ] + r * gh[j + 2 * HSZ]);
    float v = (1.0f - z) * n + z * hin[idx];
    if (WF32) hout[idx] = v;
    __nv_bfloat16 h, l;
    split_bf(v, h, l);
    ohi[idx] = h;
    olo[idx] = l;
}

// ---------------- full-tensor LayerNorm apply (+ fused bf16 split) ----------------
template <bool CONV>
__global__ void k_norm(float* __restrict__ buf, const float* __restrict__ w,
                       const float* __restrict__ b, int count, int slot,
                       __nv_bfloat16* __restrict__ ohi, __nv_bfloat16* __restrict__ olo)
{
    double sum = g_acc[slot * 2];
    double sq  = g_acc[slot * 2 + 1];
    double mu  = sum / (double)count;
    double var = sq / (double)count - mu * mu;
    float rs  = rsqrtf((float)var + 1e-5f);
    float fmu = (float)mu;
    for (int i = blockIdx.x * blockDim.x + threadIdx.x; i < count;
         i += gridDim.x * blockDim.x) {
        float v = (buf[i] - fmu) * rs * w[i] + b[i];
        if (CONV) {
            __nv_bfloat16 h, l;
            split_bf(v, h, l);
            ohi[i] = h;
            olo[i] = l;
        } else {
            buf[i] = v;
        }
    }
}

// ---------------- final dot + sigmoid + symmetric scatter ----------------
__global__ void k_out(const float* __restrict__ h3, const float* __restrict__ w4,
                      const float* __restrict__ b4, float* __restrict__ out)
{
    int w    = (blockIdx.x * blockDim.x + threadIdx.x) >> 5;
    int lane = threadIdx.x & 31;
    if (w >= NN * NN) return;
    int i = w / NN, j = w % NN;
    if (i == j) { if (lane == 0) out[w] = 0.f; return; }
    int i0 = min(i, j), j0 = max(i, j);
    int p = i0 * (NN - 1) - i0 * (i0 - 1) / 2 + (j0 - i0 - 1);
    const float* hr = h3 + (size_t)p * H2;
    float s = 0.f;
    for (int t = lane; t < H2; t += 32) s += hr[t] * w4[t];
#pragma unroll
    for (int off = 16; off; off >>= 1) s += __shfl_down_sync(0xffffffffu, s, off);
    if (lane == 0) out[w] = 1.0f / (1.0f + expf(-(s + b4[0])));
}

// ---------------- host launch ----------------
extern "C" void kernel_launch(void* const* d_in, const int* in_sizes, int n_in,
                              void* d_out, int out_size)
{
    const float* x    = (const float*)d_in[0];
    const float* hid  = (const float*)d_in[1];
    const float* Wih  = (const float*)d_in[2];
    const float* Whh  = (const float*)d_in[3];
    const float* bih  = (const float*)d_in[4];
    const float* bhh  = (const float*)d_in[5];
    const float* W1   = (const float*)d_in[6];
    const float* b1   = (const float*)d_in[7];
    const float* ln1w = (const float*)d_in[8];
    const float* ln1b = (const float*)d_in[9];
    const float* W2   = (const float*)d_in[10];
    const float* b2   = (const float*)d_in[11];
    const float* ln2w = (const float*)d_in[12];
    const float* ln2b = (const float*)d_in[13];
    const float* W3   = (const float*)d_in[14];
    const float* b3   = (const float*)d_in[15];
    const float* ln3w = (const float*)d_in[16];
    const float* ln3b = (const float*)d_in[17];
    const float* W4   = (const float*)d_in[18];
    const float* b4   = (const float*)d_in[19];
    float* out = (float*)d_out;

    float *p_gi, *p_gh, *p_h, *p_y;
    __nv_bfloat16 *p_ahi, *p_alo, *p_bhi, *p_blo;
    cudaGetSymbolAddress((void**)&p_gi,  g_gi);
    cudaGetSymbolAddress((void**)&p_gh,  g_gh);
    cudaGetSymbolAddress((void**)&p_h,   g_h);
    cudaGetSymbolAddress((void**)&p_y,   g_y);
    cudaGetSymbolAddress((void**)&p_ahi, g_ahi);
    cudaGetSymbolAddress((void**)&p_alo, g_alo);
    cudaGetSymbolAddress((void**)&p_bhi, g_bhi);
    cudaGetSymbolAddress((void**)&p_blo, g_blo);
    float* p_t  = p_gh;                    // [PP, H2]
    float* p_t2 = p_gh + (size_t)PP * H2;  // [PP, H2]

    cudaFuncSetAttribute(k_bgemm<false, -1>, cudaFuncAttributeMaxDynamicSharedMemorySize, GSMEM);
    cudaFuncSetAttribute(k_bgemm<true, 0>,   cudaFuncAttributeMaxDynamicSharedMemorySize, GSMEM);
    cudaFuncSetAttribute(k_bgemm<true, 1>,   cudaFuncAttributeMaxDynamicSharedMemorySize, GSMEM);
    cudaFuncSetAttribute(k_bgemm<true, 2>,   cudaFuncAttributeMaxDynamicSharedMemorySize, GSMEM);

    const int MB = (PP + 127) / 128;  // 28

    // 0) init
    k_init<<<(NN * NN + 255) / 256, 256>>>();

    // 1) gi_node = x @ Wih^T + bih  [84, 6144], K=64 (tiny, f32 path)
    k_gemm<false, -1><<<dim3(G3H / 128, 1), 256>>>(x, Wih, bih, p_gi, NN, G3H, 64);

    // 2) GRU step 1: gh = hid @ Whh^T + bhh, combine -> g_h (+ bf16 of h1)
    k_conv<<<(PP * HSZ + 255) / 256, 256>>>(hid, p_ahi, p_alo, PP * HSZ);
    k_conv<<<(G3H * HSZ + 255) / 256, 256>>>(Whh, p_bhi, p_blo, G3H * HSZ);
    k_bgemm<false, -1><<<dim3(G3H / 128, MB), 256, GSMEM>>>(
        p_ahi, p_alo, p_bhi, p_blo, bhh, p_gh, PP, G3H, HSZ);
    k_gru<0, true><<<(PP * HSZ + 255) / 256, 256>>>(hid, p_h, p_ahi, p_alo);

    // 3) GRU step 2: gh = h1 @ Whh^T + bhh, combine -> bf16 of h2
    k_bgemm<false, -1><<<dim3(G3H / 128, MB), 256, GSMEM>>>(
        p_ahi, p_alo, p_bhi, p_blo, bhh, p_gh, PP, G3H, HSZ);
    k_gru<1, false><<<(PP * HSZ + 255) / 256, 256>>>(p_h, p_h, p_ahi, p_alo);

    // 4) layer 1: relu(h2 @ W1^T + b1) -> g_y, LN stats fused; LN emits bf16 of y
    k_conv<<<(HSZ * HSZ + 255) / 256, 256>>>(W1, p_bhi, p_blo, HSZ * HSZ);
    k_bgemm<true, 0><<<dim3(HSZ / 128, MB), 256, GSMEM>>>(
        p_ahi, p_alo, p_bhi, p_blo, b1, p_y, PP, HSZ, HSZ);
    k_norm<true><<<2048, 256>>>(p_y, ln1w, ln1b, PP * HSZ, 0, p_ahi, p_alo);

    // 5) layer 2: relu(y @ W2^T + b2) -> t, LN emits bf16 of t
    k_conv<<<(H2 * HSZ + 255) / 256, 256>>>(W2, p_bhi, p_blo, H2 * HSZ);
    k_bgemm<true, 1><<<dim3(H2 / 128, MB), 256, GSMEM>>>(
        p_ahi, p_alo, p_bhi, p_blo, b2, p_t, PP, H2, HSZ);
    k_norm<true><<<2048, 256>>>(p_t, ln2w, ln2b, PP * H2, 1, p_ahi, p_alo);

    // 6) layer 3: relu(t @ W3^T + b3) -> t2, LN in place (f32 for k_out)
    k_conv<<<(H2 * H2 + 255) / 256, 256>>>(W3, p_bhi, p_blo, H2 * H2);
    k_bgemm<true, 2><<<dim3(H2 / 128, MB), 256, GSMEM>>>(
        p_ahi, p_alo, p_bhi, p_blo, b3, p_t2, PP, H2, H2);
    k_norm<false><<<2048, 256>>>(p_t2, ln3w, ln3b, PP * H2, 2, 0, 0);

    // 7) output
    k_out<<<(NN * NN * 32 + 255) / 256, 256>>>(p_t2, W4, b4, out);
}